// round 1
// baseline (speedup 1.0000x reference)
#include <cuda_runtime.h>
#include <cuda_bf16.h>
#include <math.h>

// Problem constants
#define B_SZ   1024
#define M_SZ   200000
#define D_SZ   64
#define SPLITS 37
#define CHUNK  5406          // ceil(200000/37); last split = 5384
#define QTILES 16            // 1024 / 64

// Scratch (static __device__ — no allocation allowed)
__device__ float g_Opart[SPLITS][B_SZ][D_SZ];   // ~9.7 MB
__device__ float g_lpart[SPLITS][B_SZ];
__device__ int   g_read_only;

// ---------------------------------------------------------------------------
// Kernel 1: copy values -> out new_values region (float4 grid-stride)
// ---------------------------------------------------------------------------
__global__ void emn_copy_vals(const float4* __restrict__ src, float4* __restrict__ dst, int n4) {
    for (int i = blockIdx.x * blockDim.x + threadIdx.x; i < n4; i += gridDim.x * blockDim.x)
        dst[i] = src[i];
}

// ---------------------------------------------------------------------------
// Kernel 2: read_only flag = all(mem_idx == 0)
// ---------------------------------------------------------------------------
__global__ void emn_flag(const int* __restrict__ mem_idx) {
    __shared__ int any_nz;
    if (threadIdx.x == 0) any_nz = 0;
    __syncthreads();
    for (int i = threadIdx.x; i < B_SZ; i += blockDim.x)
        if (mem_idx[i] != 0) any_nz = 1;   // benign race, all write 1
    __syncthreads();
    if (threadIdx.x == 0) g_read_only = (any_nz == 0);
}

// ---------------------------------------------------------------------------
// Kernel 3: gated erase/add scatter (last-index-wins on duplicate idx)
// One block per batch row, 64 threads (one per feature d).
// ---------------------------------------------------------------------------
__global__ void emn_scatter(const int* __restrict__ mem_idx,
                            const float* __restrict__ input,
                            const float* __restrict__ values,
                            const float* __restrict__ Wew, const float* __restrict__ Web,
                            const float* __restrict__ Waw, const float* __restrict__ Wab,
                            float* __restrict__ newvals) {
    if (g_read_only) return;
    const int b = blockIdx.x;
    const int idx = mem_idx[b];
    __shared__ int dup;
    __shared__ float xin[D_SZ];
    if (threadIdx.x == 0) dup = 0;
    xin[threadIdx.x] = input[b * D_SZ + threadIdx.x];
    __syncthreads();
    // any later batch element with the same index wins instead
    for (int bp = b + 1 + threadIdx.x; bp < B_SZ; bp += 64)
        if (mem_idx[bp] == idx) dup = 1;
    __syncthreads();
    if (dup) return;

    const int d = threadIdx.x;
    float e = Web[d], a = Wab[d];
#pragma unroll
    for (int k = 0; k < D_SZ; k++) {
        const float x = xin[k];
        e = fmaf(x, Wew[d * D_SZ + k], e);
        a = fmaf(x, Waw[d * D_SZ + k], a);
    }
    e = 1.0f / (1.0f + __expf(-e));   // sigmoid
    a = tanhf(a);
    const long off = (long)idx * D_SZ + d;
    newvals[off] = (1.0f - e) * values[off] + a;
}

// ---------------------------------------------------------------------------
// Kernel 4: attention partials (exp-sum streaming; no max subtraction needed:
// scores = input . values rows, |score| <~ 0.3 given the data distribution).
// Grid: (QTILES, SPLITS), 256 threads, 64x64 tiles, 4x4 register tiles.
// smem (dynamic, 69,888 B): Qs[k][r], Kt[d][c], Vs[c][d], Ps[c][r], lred[64]
// all rows padded to 68 floats (keeps float4 alignment, spreads banks).
// ---------------------------------------------------------------------------
#define PAD 68
#define SM_QS 0
#define SM_KT (64 * PAD)
#define SM_VS (2 * 64 * PAD)
#define SM_PS (3 * 64 * PAD)
#define SM_LR (4 * 64 * PAD)
#define SMEM_FLOATS (4 * 64 * PAD + 64)

__global__ void __launch_bounds__(256)
emn_attn_partial(const float* __restrict__ input, const float* __restrict__ values) {
    extern __shared__ float sm[];
    float* Qs = sm + SM_QS;
    float* Kt = sm + SM_KT;
    float* Vs = sm + SM_VS;
    float* Ps = sm + SM_PS;
    float* lred = sm + SM_LR;

    const int tid = threadIdx.x;
    const int tx = tid & 15;        // 0..15 -> cols (c or d), 4 each
    const int ty = tid >> 4;        // 0..15 -> rows (r), 4 each
    const int qb = blockIdx.x << 6; // q-tile base row
    const int s  = blockIdx.y;      // kv split
    const int kv0 = s * CHUNK;
    const int kv1 = min(M_SZ, kv0 + CHUNK);

    // Load Q tile transposed: Qs[k][r] = input[qb+r][k]
    for (int f = tid; f < 1024; f += 256) {
        const int r = f >> 4;
        const int k4 = (f & 15) << 2;
        const float4 q = *(const float4*)(input + (qb + r) * D_SZ + k4);
        Qs[(k4 + 0) * PAD + r] = q.x;
        Qs[(k4 + 1) * PAD + r] = q.y;
        Qs[(k4 + 2) * PAD + r] = q.z;
        Qs[(k4 + 3) * PAD + r] = q.w;
    }
    if (tid < 64) lred[tid] = 0.0f;

    float acc[4][4] = {};   // O[r][d]
    float lsum[4]   = {};   // sum of exp per row

    for (int kv = kv0; kv < kv1; kv += 64) {
        const int kc = min(64, kv1 - kv);
        __syncthreads();    // previous iteration done with Kt/Vs/Ps
        // Load values tile: Vs[c][d] (natural) and Kt[d][c] (transposed)
        for (int f = tid; f < 1024; f += 256) {
            const int c = f >> 4;
            const int d4 = (f & 15) << 2;
            float4 v;
            if (c < kc) v = *(const float4*)(values + (long)(kv + c) * D_SZ + d4);
            else        v = make_float4(0.f, 0.f, 0.f, 0.f);
            *(float4*)(Vs + c * PAD + d4) = v;
            Kt[(d4 + 0) * PAD + c] = v.x;
            Kt[(d4 + 1) * PAD + c] = v.y;
            Kt[(d4 + 2) * PAD + c] = v.z;
            Kt[(d4 + 3) * PAD + c] = v.w;
        }
        __syncthreads();

        // GEMM1: S[r][c] = sum_k Q[r][k] * K[c][k]
        float sr[4][4] = {};
#pragma unroll 16
        for (int k = 0; k < 64; k++) {
            const float4 q = *(const float4*)(Qs + k * PAD + (ty << 2));
            const float4 kk = *(const float4*)(Kt + k * PAD + (tx << 2));
            sr[0][0] = fmaf(q.x, kk.x, sr[0][0]); sr[0][1] = fmaf(q.x, kk.y, sr[0][1]);
            sr[0][2] = fmaf(q.x, kk.z, sr[0][2]); sr[0][3] = fmaf(q.x, kk.w, sr[0][3]);
            sr[1][0] = fmaf(q.y, kk.x, sr[1][0]); sr[1][1] = fmaf(q.y, kk.y, sr[1][1]);
            sr[1][2] = fmaf(q.y, kk.z, sr[1][2]); sr[1][3] = fmaf(q.y, kk.w, sr[1][3]);
            sr[2][0] = fmaf(q.z, kk.x, sr[2][0]); sr[2][1] = fmaf(q.z, kk.y, sr[2][1]);
            sr[2][2] = fmaf(q.z, kk.z, sr[2][2]); sr[2][3] = fmaf(q.z, kk.w, sr[2][3]);
            sr[3][0] = fmaf(q.w, kk.x, sr[3][0]); sr[3][1] = fmaf(q.w, kk.y, sr[3][1]);
            sr[3][2] = fmaf(q.w, kk.z, sr[3][2]); sr[3][3] = fmaf(q.w, kk.w, sr[3][3]);
        }

        // P = exp(S), masked tail; store transposed Ps[c][r]; accumulate l
#pragma unroll
        for (int i = 0; i < 4; i++) {
#pragma unroll
            for (int j = 0; j < 4; j++) {
                const int c = (tx << 2) + j;
                const float p = (c < kc) ? __expf(sr[i][j]) : 0.0f;
                lsum[i] += p;
                Ps[c * PAD + (ty << 2) + i] = p;
            }
        }
        __syncthreads();

        // GEMM2: O[r][d] += sum_c P[r][c] * V[c][d]
#pragma unroll 16
        for (int c = 0; c < 64; c++) {
            const float4 pv = *(const float4*)(Ps + c * PAD + (ty << 2));
            const float4 vv = *(const float4*)(Vs + c * PAD + (tx << 2));
            acc[0][0] = fmaf(pv.x, vv.x, acc[0][0]); acc[0][1] = fmaf(pv.x, vv.y, acc[0][1]);
            acc[0][2] = fmaf(pv.x, vv.z, acc[0][2]); acc[0][3] = fmaf(pv.x, vv.w, acc[0][3]);
            acc[1][0] = fmaf(pv.y, vv.x, acc[1][0]); acc[1][1] = fmaf(pv.y, vv.y, acc[1][1]);
            acc[1][2] = fmaf(pv.y, vv.z, acc[1][2]); acc[1][3] = fmaf(pv.y, vv.w, acc[1][3]);
            acc[2][0] = fmaf(pv.z, vv.x, acc[2][0]); acc[2][1] = fmaf(pv.z, vv.y, acc[2][1]);
            acc[2][2] = fmaf(pv.z, vv.z, acc[2][2]); acc[2][3] = fmaf(pv.z, vv.w, acc[2][3]);
            acc[3][0] = fmaf(pv.w, vv.x, acc[3][0]); acc[3][1] = fmaf(pv.w, vv.y, acc[3][1]);
            acc[3][2] = fmaf(pv.w, vv.z, acc[3][2]); acc[3][3] = fmaf(pv.w, vv.w, acc[3][3]);
        }
    }

    // Write partial O and l
    const int r0 = ty << 2, d0 = tx << 2;
#pragma unroll
    for (int i = 0; i < 4; i++) {
        const float4 o = make_float4(acc[i][0], acc[i][1], acc[i][2], acc[i][3]);
        *(float4*)(&g_Opart[s][qb + r0 + i][d0]) = o;
        atomicAdd(&lred[r0 + i], lsum[i]);
    }
    __syncthreads();
    if (tid < 64) g_lpart[s][qb + tid] = lred[tid];
}

// ---------------------------------------------------------------------------
// Kernel 5: combine splits -> retrieved[b][d] = sum_s O / sum_s l
// ---------------------------------------------------------------------------
__global__ void emn_attn_reduce(float* __restrict__ retrieved) {
    const int b = blockIdx.x;
    const int d = threadIdx.x;
    float o = 0.0f, l = 0.0f;
#pragma unroll
    for (int s = 0; s < SPLITS; s++) {
        o += g_Opart[s][b][d];
        l += g_lpart[s][b];
    }
    retrieved[b * D_SZ + d] = o / l;
}

// ---------------------------------------------------------------------------
extern "C" void kernel_launch(void* const* d_in, const int* in_sizes, int n_in,
                              void* d_out, int out_size) {
    const int*   mem_idx = (const int*)d_in[0];
    const float* input   = (const float*)d_in[1];
    const float* values  = (const float*)d_in[2];
    const float* Wew     = (const float*)d_in[3];
    const float* Web     = (const float*)d_in[4];
    const float* Waw     = (const float*)d_in[5];
    const float* Wab     = (const float*)d_in[6];

    float* out       = (float*)d_out;
    float* retrieved = out;                    // [B, D]
    float* newvals   = out + B_SZ * D_SZ;      // [M, D]

    // 1) copy values into the output table
    emn_copy_vals<<<2048, 256>>>((const float4*)values, (float4*)newvals,
                                 (M_SZ * D_SZ) / 4);
    // 2) read-only flag
    emn_flag<<<1, 256>>>(mem_idx);
    // 3) scatter the gated updates (last-index-wins)
    emn_scatter<<<B_SZ, 64>>>(mem_idx, input, values, Wew, Web, Waw, Wab, newvals);
    // 4) attention partials
    static_assert(SMEM_FLOATS * 4 == 69888 + 256 - 256 + 0, "");  // 69,888 B
    cudaFuncSetAttribute(emn_attn_partial,
                         cudaFuncAttributeMaxDynamicSharedMemorySize,
                         SMEM_FLOATS * (int)sizeof(float));
    emn_attn_partial<<<dim3(QTILES, SPLITS), 256, SMEM_FLOATS * sizeof(float)>>>(input, values);
    // 5) combine
    emn_attn_reduce<<<B_SZ, D_SZ>>>(retrieved);
}

// round 6
// speedup vs baseline: 5.5100x; 5.5100x over previous
#include <cuda_runtime.h>
#include <cuda_bf16.h>
#include <stdint.h>
#include <math.h>

// Problem constants
#define B_SZ   1024
#define M_SZ   200000
#define D_SZ   64
#define KV_TILE 128
#define TILES_TOTAL 1563     // ceil(200000/128); last tile zero-padded
#define TPS 22               // tiles per split
#define SPLITS 74            // 8 x 74 = 592 CTAs = 2 waves @ 2 CTA/SM
#define QTILES 8             // 1024 / 128

// Static device scratch (no allocation allowed)
__device__ float g_Opart[SPLITS][B_SZ][D_SZ];                       // ~19.4 MB
__device__ float g_lpart[SPLITS][B_SZ];
__device__ float g_tilesum[TILES_TOTAL][D_SZ];                      // per-tile V column sums (fp32)
__device__ float g_vcolsum[D_SZ];                                   // global V column sums (fp32)
__device__ int   g_read_only;
__device__ __align__(16) __nv_bfloat16 g_vbf[(size_t)TILES_TOTAL * KV_TILE * D_SZ]; // 25.6MB, swizzled tiles

// ===========================================================================
// PTX helpers (family-portable only: mma.sync / ldmatrix / cp.async.bulk)
// ===========================================================================
__device__ __forceinline__ uint32_t smem_u32(const void* p) {
    uint32_t a;
    asm("{ .reg .u64 t; cvta.to.shared.u64 t, %1; cvt.u32.u64 %0, t; }" : "=r"(a) : "l"(p));
    return a;
}

// pack: lo = a, hi = b
__device__ __forceinline__ uint32_t pack_bf16(float a, float b) {
    uint32_t r;
    asm("cvt.rn.bf16x2.f32 %0, %1, %2;" : "=r"(r) : "f"(b), "f"(a));
    return r;
}

__device__ __forceinline__ void mma_bf16(float c[4], const uint32_t a[4],
                                         uint32_t b0, uint32_t b1) {
    asm volatile("mma.sync.aligned.m16n8k16.row.col.f32.bf16.bf16.f32 "
        "{%0,%1,%2,%3}, {%4,%5,%6,%7}, {%8,%9}, {%0,%1,%2,%3};"
        : "+f"(c[0]), "+f"(c[1]), "+f"(c[2]), "+f"(c[3])
        : "r"(a[0]), "r"(a[1]), "r"(a[2]), "r"(a[3]), "r"(b0), "r"(b1));
}

__device__ __forceinline__ void ldsm4(uint32_t r[4], uint32_t addr) {
    asm volatile("ldmatrix.sync.aligned.m8n8.x4.shared.b16 {%0,%1,%2,%3}, [%4];"
        : "=r"(r[0]), "=r"(r[1]), "=r"(r[2]), "=r"(r[3]) : "r"(addr));
}
__device__ __forceinline__ void ldsm4t(uint32_t r[4], uint32_t addr) {
    asm volatile("ldmatrix.sync.aligned.m8n8.x4.trans.shared.b16 {%0,%1,%2,%3}, [%4];"
        : "=r"(r[0]), "=r"(r[1]), "=r"(r[2]), "=r"(r[3]) : "r"(addr));
}

#define MBARRIER_INIT(mbar, cnt) \
    asm volatile("mbarrier.init.shared.b64 [%0], %1;" :: "r"((uint32_t)(mbar)), "r"((uint32_t)(cnt)) : "memory")
#define MBARRIER_EXPECT_TX(mbar, bytes) \
    asm volatile("mbarrier.arrive.expect_tx.shared.b64 _, [%0], %1;" :: "r"((uint32_t)(mbar)), "r"((uint32_t)(bytes)) : "memory")
#define BULK_G2S(dst, src, bytes, mbar) \
    asm volatile("cp.async.bulk.shared::cta.global.mbarrier::complete_tx::bytes [%0], [%1], %2, [%3];" \
        :: "r"((uint32_t)(dst)), "l"(src), "r"((uint32_t)(bytes)), "r"((uint32_t)(mbar)) : "memory")

#define MBARRIER_WAIT_PARITY(mbar_addr, parity) do { \
    uint32_t _m = (uint32_t)(mbar_addr); uint32_t _p = (uint32_t)(parity); uint32_t _d; \
    asm volatile("{\n\t.reg .pred p;\n\t" \
        "mbarrier.try_wait.parity.acquire.cta.shared::cta.b64 p, [%1], %2;\n\t" \
        "selp.b32 %0, 1, 0, p;\n\t}" : "=r"(_d) : "r"(_m), "r"(_p) : "memory"); \
    if (!_d) { \
        asm volatile("{\n\t.reg .pred P1;\n\t" \
            "WAIT_LOOP_%=:\n\t" \
            "mbarrier.try_wait.parity.acquire.cta.shared::cta.b64 P1, [%0], %1, 0x989680;\n\t" \
            "@P1 bra.uni WAIT_DONE_%=;\n\t" \
            "bra.uni WAIT_LOOP_%=;\n\t" \
            "WAIT_DONE_%=:\n\t}" :: "r"(_m), "r"(_p) : "memory"); \
    } \
} while (0)

#define STS128(r0, r1, r2, r3, addr) \
    asm volatile("st.shared.v4.b32 [%0], {%1, %2, %3, %4};" \
        :: "r"(addr), "r"(r0), "r"(r1), "r"(r2), "r"(r3) : "memory")

// ===========================================================================
// Kernel 1: values fp32 -> (a) fp32 copy into out table, (b) bf16 swizzled
// tile table g_vbf, (c) per-tile fp32 column sums (deterministic order).
// Grid: TILES_TOTAL CTAs x 256 threads. Thread covers half a row (32 floats).
// ===========================================================================
__global__ void emn_cvt(const float* __restrict__ values, float* __restrict__ newvals) {
    const int t = blockIdx.x;
    const int tid = threadIdx.x;
    const int row = tid >> 1;
    const int half = tid & 1;
    const long gr = (long)t * KV_TILE + row;

    float4 v[8];
    if (gr < (long)M_SZ) {
        const float4* src = (const float4*)(values + gr * D_SZ + half * 32);
#pragma unroll
        for (int i = 0; i < 8; i++) v[i] = src[i];
        float4* dst = (float4*)(newvals + gr * D_SZ + half * 32);
#pragma unroll
        for (int i = 0; i < 8; i++) dst[i] = v[i];
    } else {
#pragma unroll
        for (int i = 0; i < 8; i++) v[i] = make_float4(0.f, 0.f, 0.f, 0.f);
    }

    char* tb = ((char*)g_vbf) + (size_t)t * 16384;
    const uint32_t xm = (uint32_t)((row & 7) << 4);
#pragma unroll
    for (int i = 0; i < 4; i++) {
        uint4 u;
        u.x = pack_bf16(v[2 * i].x, v[2 * i].y);
        u.y = pack_bf16(v[2 * i].z, v[2 * i].w);
        u.z = pack_bf16(v[2 * i + 1].x, v[2 * i + 1].y);
        u.w = pack_bf16(v[2 * i + 1].z, v[2 * i + 1].w);
        const uint32_t off = (uint32_t)(row * 128 + half * 64 + i * 16);
        *(uint4*)(tb + (off ^ xm)) = u;
    }

    // per-tile column sums in fp32 (fixed sequential order -> deterministic);
    // rows just touched, so these reads hit L1/L2.
    if (tid < D_SZ) {
        int nrows = M_SZ - t * KV_TILE;
        if (nrows > KV_TILE) nrows = KV_TILE;
        const float* col = values + (long)t * KV_TILE * D_SZ + tid;
        float s = 0.f;
        for (int r = 0; r < nrows; r++) s += col[(long)r * D_SZ];
        g_tilesum[t][tid] = s;
    }
}

// ===========================================================================
// Kernel 1b: reduce per-tile sums -> global column sums (deterministic).
// ===========================================================================
__global__ void emn_colsum() {
    const int w = (blockIdx.x * (blockDim.x >> 5)) + (threadIdx.x >> 5);
    const int lane = threadIdx.x & 31;
    if (w >= D_SZ) return;
    float s = 0.f;
    for (int t = lane; t < TILES_TOTAL; t += 32) s += g_tilesum[t][w];
#pragma unroll
    for (int o = 16; o; o >>= 1) s += __shfl_xor_sync(0xffffffffu, s, o);
    if (lane == 0) g_vcolsum[w] = s;
}

// ===========================================================================
// Kernel 2: read_only flag
// ===========================================================================
__global__ void emn_flag(const int* __restrict__ mem_idx) {
    __shared__ int any_nz;
    if (threadIdx.x == 0) any_nz = 0;
    __syncthreads();
    for (int i = threadIdx.x; i < B_SZ; i += blockDim.x)
        if (mem_idx[i] != 0) any_nz = 1;
    __syncthreads();
    if (threadIdx.x == 0) g_read_only = (any_nz == 0);
}

// ===========================================================================
// Kernel 3: gated erase/add scatter (last-index-wins)
// ===========================================================================
__global__ void emn_scatter(const int* __restrict__ mem_idx,
                            const float* __restrict__ input,
                            const float* __restrict__ values,
                            const float* __restrict__ Wew, const float* __restrict__ Web,
                            const float* __restrict__ Waw, const float* __restrict__ Wab,
                            float* __restrict__ newvals) {
    if (g_read_only) return;
    const int b = blockIdx.x;
    const int idx = mem_idx[b];
    __shared__ int dup;
    __shared__ float xin[D_SZ];
    if (threadIdx.x == 0) dup = 0;
    xin[threadIdx.x] = input[b * D_SZ + threadIdx.x];
    __syncthreads();
    for (int bp = b + 1 + threadIdx.x; bp < B_SZ; bp += 64)
        if (mem_idx[bp] == idx) dup = 1;
    __syncthreads();
    if (dup) return;

    const int d = threadIdx.x;
    float e = Web[d], a = Wab[d];
#pragma unroll
    for (int k = 0; k < D_SZ; k++) {
        const float x = xin[k];
        e = fmaf(x, Wew[d * D_SZ + k], e);
        a = fmaf(x, Waw[d * D_SZ + k], a);
    }
    e = 1.0f / (1.0f + __expf(-e));
    a = tanhf(a);
    const long off = (long)idx * D_SZ + d;
    newvals[off] = (1.0f - e) * values[off] + a;
}

// ===========================================================================
// Kernel 4: flash attention partials via warp-level HMMA (mma.sync bf16).
// Precision scheme:
//   * Q split into q_hi + q_lo (two bf16 tiles) -> S computed to ~fp32 quality
//     against bf16 K. (The q-rounding error is CORRELATED with the retrieved
//     signal q_d*sigma_v^2 and was the 1.3e-3 failure; the split kills it.)
//   * P_dev = exp(S)-1 (|P_dev|~0.03) through GEMM2; the O(1) part of exp is
//     the exact fp32 V column sum, added in the combine kernel.
// Grid (QTILES=8, SPLITS=74), 256 threads (8 warps), 2 CTAs/SM.
// ===========================================================================
__global__ void __launch_bounds__(256, 2)
emn_attn(const float* __restrict__ input) {
    extern __shared__ char dsm[];   // Qhi 18432 | Qlo 18432 | K0 16384 | K1 16384
    __shared__ __align__(8) unsigned long long s_mbar[2];

    const uint32_t smQ  = smem_u32(dsm);
    const uint32_t smQl = smQ + 18432u;
    const uint32_t smK[2] = { smQ + 36864u, smQ + 53248u };
    const uint32_t mb[2] = { smem_u32(&s_mbar[0]), smem_u32(&s_mbar[1]) };

    const int tid  = threadIdx.x;
    const int wid  = tid >> 5;
    const int lane = tid & 31;
    const int gi   = lane >> 2;       // groupID
    const int tig  = lane & 3;        // thread-in-group
    const int wbase = wid * 16;       // q rows of this warp within the tile
    const int qb = blockIdx.x * 128;
    const int s  = blockIdx.y;
    const int t0 = s * TPS;
    int ntiles = TILES_TOTAL - t0;
    if (ntiles < 0) ntiles = 0;
    if (ntiles > TPS) ntiles = TPS;

    // --- Q tile -> (q_hi, q_lo) bf16 smem, 144B row stride ---
    {
        const int row = tid >> 1;
        const int half = tid & 1;
        const float4* qp = (const float4*)(input + (qb + row) * D_SZ + half * 32);
        float4 q[8];
#pragma unroll
        for (int i = 0; i < 8; i++) q[i] = qp[i];
        const uint32_t base = smQ + (uint32_t)(row * 144 + half * 64);
#pragma unroll
        for (int i = 0; i < 4; i++) {
            float x0 = q[2 * i].x, x1 = q[2 * i].y, x2 = q[2 * i].z, x3 = q[2 * i].w;
            float x4 = q[2 * i + 1].x, x5 = q[2 * i + 1].y, x6 = q[2 * i + 1].z, x7 = q[2 * i + 1].w;
            uint32_t h0 = pack_bf16(x0, x1);
            uint32_t h1 = pack_bf16(x2, x3);
            uint32_t h2 = pack_bf16(x4, x5);
            uint32_t h3 = pack_bf16(x6, x7);
            STS128(h0, h1, h2, h3, base + i * 16);
            // residuals
            __nv_bfloat162 b01 = *(__nv_bfloat162*)&h0;
            __nv_bfloat162 b23 = *(__nv_bfloat162*)&h1;
            __nv_bfloat162 b45 = *(__nv_bfloat162*)&h2;
            __nv_bfloat162 b67 = *(__nv_bfloat162*)&h3;
            uint32_t l0 = pack_bf16(x0 - __bfloat162float(b01.x), x1 - __bfloat162float(b01.y));
            uint32_t l1 = pack_bf16(x2 - __bfloat162float(b23.x), x3 - __bfloat162float(b23.y));
            uint32_t l2 = pack_bf16(x4 - __bfloat162float(b45.x), x5 - __bfloat162float(b45.y));
            uint32_t l3 = pack_bf16(x6 - __bfloat162float(b67.x), x7 - __bfloat162float(b67.y));
            STS128(l0, l1, l2, l3, base + 18432u + i * 16);
        }
    }
    if (tid < 2) MBARRIER_INIT(mb[tid], 1);
    __syncthreads();

    // --- Q fragments: hi and lo (ldmatrix x4 per 16-wide k block) ---
    uint32_t qa[4][4], ql[4][4];
    {
        const int rQ = wbase + (lane & 7) + (((lane >> 3) & 1) << 3);
        const uint32_t qoff = (uint32_t)(rQ * 144 + (lane >> 4) * 16);
#pragma unroll
        for (int kb = 0; kb < 4; kb++) ldsm4(qa[kb], smQ + qoff + kb * 32);
#pragma unroll
        for (int kb = 0; kb < 4; kb++) ldsm4(ql[kb], smQl + qoff + kb * 32);
    }

    // --- prologue: tile 0 into buffer 0 ---
    int ph[2] = { 0, 0 };
    if (ntiles > 0 && tid == 0) {
        MBARRIER_EXPECT_TX(mb[0], 16384);
        BULK_G2S(smK[0], (const char*)g_vbf + (size_t)t0 * 16384, 16384, mb[0]);
    }

    const uint32_t xorm = (uint32_t)((lane & 7) << 4);
    const uint32_t klo_a = (uint32_t)((lane & 7) * 128) + ((((lane >> 3) & 3) << 4) ^ xorm);
    const uint32_t klo_b = (uint32_t)((lane & 7) * 128) + ((64u + (((lane >> 3) & 3) << 4)) ^ xorm);
    const uint32_t vlo   = (uint32_t)((lane & 15) * 128);

    float oacc[8][4];
#pragma unroll
    for (int n = 0; n < 8; n++)
#pragma unroll
        for (int i = 0; i < 4; i++) oacc[n][i] = 0.f;
    float ls0 = 0.f, ls1 = 0.f;
    int buf = 0;

    for (int it = 0; it < ntiles; ++it) {
        const uint32_t kbase = smK[buf];
        MBARRIER_WAIT_PARITY(mb[buf], ph[buf]);
        ph[buf] ^= 1;

        if (tid == 0 && it + 1 < ntiles) {
            MBARRIER_EXPECT_TX(mb[buf ^ 1], 16384);
            BULK_G2S(smK[buf ^ 1], (const char*)g_vbf + (size_t)(t0 + it + 1) * 16384,
                     16384, mb[buf ^ 1]);
        }

        const int kv = (t0 + it) * KV_TILE;
        const int lim = M_SZ - kv;            // >= 128 except global last tile
        const bool full = (lim >= KV_TILE);

        // --- GEMM1: S = (Qhi + Qlo) @ K^T ; epilogue: P_dev = exp(S)-1 ---
        uint32_t pf[8][4];
#pragma unroll
        for (int j = 0; j < 16; j++) {
            uint32_t ba[4], bb[4];
            ldsm4(ba, kbase + (uint32_t)(j * 1024) + klo_a);
            ldsm4(bb, kbase + (uint32_t)(j * 1024) + klo_b);
            float c[4] = { 0.f, 0.f, 0.f, 0.f };
            mma_bf16(c, ql[0], ba[0], ba[1]);
            mma_bf16(c, ql[1], ba[2], ba[3]);
            mma_bf16(c, ql[2], bb[0], bb[1]);
            mma_bf16(c, ql[3], bb[2], bb[3]);
            mma_bf16(c, qa[0], ba[0], ba[1]);
            mma_bf16(c, qa[1], ba[2], ba[3]);
            mma_bf16(c, qa[2], bb[0], bb[1]);
            mma_bf16(c, qa[3], bb[2], bb[3]);

            float e0, e1, e2, e3;
            if (full) {
                e0 = __expf(c[0]) - 1.0f; e1 = __expf(c[1]) - 1.0f;
                e2 = __expf(c[2]) - 1.0f; e3 = __expf(c[3]) - 1.0f;
            } else {
                const int col = (j << 3) + (tig << 1);
                e0 = (col     < lim) ? __expf(c[0]) - 1.0f : 0.f;
                e1 = (col + 1 < lim) ? __expf(c[1]) - 1.0f : 0.f;
                e2 = (col     < lim) ? __expf(c[2]) - 1.0f : 0.f;
                e3 = (col + 1 < lim) ? __expf(c[3]) - 1.0f : 0.f;
            }
            ls0 += e0 + e1;
            ls1 += e2 + e3;
            const uint32_t p01 = pack_bf16(e0, e1);
            const uint32_t p23 = pack_bf16(e2, e3);
            if (!(j & 1)) { pf[j >> 1][0] = p01; pf[j >> 1][1] = p23; }
            else          { pf[j >> 1][2] = p01; pf[j >> 1][3] = p23; }
        }

        // --- GEMM2: O += P_dev @ V (same smem tile via ldmatrix.trans) ---
#pragma unroll
        for (int kb = 0; kb < 8; kb++) {
#pragma unroll
            for (int n = 0; n < 8; n += 2) {
                uint32_t bv[4];
                ldsm4t(bv, kbase + vlo + (uint32_t)(kb * 2048)
                             + ((((uint32_t)(n + (lane >> 4))) << 4) ^ xorm));
                mma_bf16(oacc[n],     pf[kb], bv[0], bv[1]);
                mma_bf16(oacc[n + 1], pf[kb], bv[2], bv[3]);
            }
        }

        __syncthreads();   // everyone done reading this buffer before refill
        buf ^= 1;
    }

    // --- write O partials ---
    const int r0 = qb + wbase + gi;
#pragma unroll
    for (int n = 0; n < 8; n++) {
        const int col = n * 8 + tig * 2;
        *(float2*)&g_Opart[s][r0][col]     = make_float2(oacc[n][0], oacc[n][1]);
        *(float2*)&g_Opart[s][r0 + 8][col] = make_float2(oacc[n][2], oacc[n][3]);
    }
    // --- row-sum partials ---
    ls0 += __shfl_xor_sync(0xffffffffu, ls0, 1);
    ls0 += __shfl_xor_sync(0xffffffffu, ls0, 2);
    ls1 += __shfl_xor_sync(0xffffffffu, ls1, 1);
    ls1 += __shfl_xor_sync(0xffffffffu, ls1, 2);
    if (tig == 0) {
        g_lpart[s][r0]     = ls0;
        g_lpart[s][r0 + 8] = ls1;
    }
}

// ===========================================================================
// Kernel 5: combine splits.
// retrieved[b][d] = (colsum[d] + sum_s O_s) / (M + sum_s l_s)
// ===========================================================================
__global__ void emn_attn_reduce(float* __restrict__ retrieved) {
    const int b = blockIdx.x;
    const int d = threadIdx.x;
    float o = g_vcolsum[d];
    float l = (float)M_SZ;
#pragma unroll 2
    for (int s = 0; s < SPLITS; s++) {
        o += g_Opart[s][b][d];
        l += g_lpart[s][b];
    }
    retrieved[b * D_SZ + d] = o / l;
}

// ===========================================================================
extern "C" void kernel_launch(void* const* d_in, const int* in_sizes, int n_in,
                              void* d_out, int out_size) {
    const int*   mem_idx = (const int*)d_in[0];
    const float* input   = (const float*)d_in[1];
    const float* values  = (const float*)d_in[2];
    const float* Wew     = (const float*)d_in[3];
    const float* Web     = (const float*)d_in[4];
    const float* Waw     = (const float*)d_in[5];
    const float* Wab     = (const float*)d_in[6];

    float* out       = (float*)d_out;
    float* retrieved = out;                    // [B, D]
    float* newvals   = out + B_SZ * D_SZ;      // [M, D]

    // 1) fused: copy values -> out table + bf16 swizzled tiles + tile colsums
    emn_cvt<<<TILES_TOTAL, 256>>>(values, newvals);
    // 1b) global column sums (deterministic tree)
    emn_colsum<<<8, 256>>>();
    // 2) read-only flag
    emn_flag<<<1, 256>>>(mem_idx);
    // 3) gated scatter
    emn_scatter<<<B_SZ, 64>>>(mem_idx, input, values, Wew, Web, Waw, Wab, newvals);
    // 4) attention partials (tensor cores, Q hi/lo split)
    const int dyn_smem = 2 * 18432 + 2 * 16384;    // 69632 B
    cudaFuncSetAttribute(emn_attn, cudaFuncAttributeMaxDynamicSharedMemorySize, dyn_smem);
    emn_attn<<<dim3(QTILES, SPLITS), 256, dyn_smem>>>(input);
    // 5) combine
    emn_attn_reduce<<<B_SZ, D_SZ>>>(retrieved);
}

// round 8
// speedup vs baseline: 6.9140x; 1.2548x over previous
#include <cuda_runtime.h>
#include <cuda_fp16.h>
#include <stdint.h>
#include <math.h>

// Problem constants
#define B_SZ   1024
#define M_SZ   200000
#define D_SZ   64
#define KV_TILE 128
#define TILES_TOTAL 1563     // ceil(200000/128); last tile zero-padded
#define TPS 22               // tiles per split
#define SPLITS 74            // 8 x 74 = 592 CTAs = 2 waves @ 2 CTA/SM
#define QTILES 8             // 1024 / 128

// Static device scratch (no allocation allowed)
__device__ float g_Opart[SPLITS][B_SZ][D_SZ];                       // ~19.4 MB
__device__ float g_lpart[SPLITS][B_SZ];
__device__ float g_tilesum[TILES_TOTAL][D_SZ];                      // per-tile V column sums (fp32)
__device__ float g_vcolsum[D_SZ];                                   // global V column sums (fp32)
__device__ float g_ea[2][B_SZ][D_SZ];                               // erase/add gate values
__device__ int   g_read_only;
__device__ __align__(16) __half g_vbf[(size_t)TILES_TOTAL * KV_TILE * D_SZ]; // 25.6MB fp16, swizzled tiles

// ===========================================================================
// PTX helpers (family-portable only: mma.sync / ldmatrix / cp.async.bulk)
// ===========================================================================
__device__ __forceinline__ uint32_t smem_u32(const void* p) {
    uint32_t a;
    asm("{ .reg .u64 t; cvta.to.shared.u64 t, %1; cvt.u32.u64 %0, t; }" : "=r"(a) : "l"(p));
    return a;
}

// pack fp16x2: lo = a, hi = b
__device__ __forceinline__ uint32_t pack_h(float a, float b) {
    uint32_t r;
    asm("cvt.rn.f16x2.f32 %0, %1, %2;" : "=r"(r) : "f"(b), "f"(a));
    return r;
}

__device__ __forceinline__ void mma_f16(float c[4], const uint32_t a[4],
                                        uint32_t b0, uint32_t b1) {
    asm volatile("mma.sync.aligned.m16n8k16.row.col.f32.f16.f16.f32 "
        "{%0,%1,%2,%3}, {%4,%5,%6,%7}, {%8,%9}, {%0,%1,%2,%3};"
        : "+f"(c[0]), "+f"(c[1]), "+f"(c[2]), "+f"(c[3])
        : "r"(a[0]), "r"(a[1]), "r"(a[2]), "r"(a[3]), "r"(b0), "r"(b1));
}

__device__ __forceinline__ void ldsm4(uint32_t r[4], uint32_t addr) {
    asm volatile("ldmatrix.sync.aligned.m8n8.x4.shared.b16 {%0,%1,%2,%3}, [%4];"
        : "=r"(r[0]), "=r"(r[1]), "=r"(r[2]), "=r"(r[3]) : "r"(addr));
}
__device__ __forceinline__ void ldsm4t(uint32_t r[4], uint32_t addr) {
    asm volatile("ldmatrix.sync.aligned.m8n8.x4.trans.shared.b16 {%0,%1,%2,%3}, [%4];"
        : "=r"(r[0]), "=r"(r[1]), "=r"(r[2]), "=r"(r[3]) : "r"(addr));
}

#define MBARRIER_INIT(mbar, cnt) \
    asm volatile("mbarrier.init.shared.b64 [%0], %1;" :: "r"((uint32_t)(mbar)), "r"((uint32_t)(cnt)) : "memory")
#define MBARRIER_EXPECT_TX(mbar, bytes) \
    asm volatile("mbarrier.arrive.expect_tx.shared.b64 _, [%0], %1;" :: "r"((uint32_t)(mbar)), "r"((uint32_t)(bytes)) : "memory")
#define BULK_G2S(dst, src, bytes, mbar) \
    asm volatile("cp.async.bulk.shared::cta.global.mbarrier::complete_tx::bytes [%0], [%1], %2, [%3];" \
        :: "r"((uint32_t)(dst)), "l"(src), "r"((uint32_t)(bytes)), "r"((uint32_t)(mbar)) : "memory")

#define MBARRIER_WAIT_PARITY(mbar_addr, parity) do { \
    uint32_t _m = (uint32_t)(mbar_addr); uint32_t _p = (uint32_t)(parity); uint32_t _d; \
    asm volatile("{\n\t.reg .pred p;\n\t" \
        "mbarrier.try_wait.parity.acquire.cta.shared::cta.b64 p, [%1], %2;\n\t" \
        "selp.b32 %0, 1, 0, p;\n\t}" : "=r"(_d) : "r"(_m), "r"(_p) : "memory"); \
    if (!_d) { \
        asm volatile("{\n\t.reg .pred P1;\n\t" \
            "WAIT_LOOP_%=:\n\t" \
            "mbarrier.try_wait.parity.acquire.cta.shared::cta.b64 P1, [%0], %1, 0x989680;\n\t" \
            "@P1 bra.uni WAIT_DONE_%=;\n\t" \
            "bra.uni WAIT_LOOP_%=;\n\t" \
            "WAIT_DONE_%=:\n\t}" :: "r"(_m), "r"(_p) : "memory"); \
    } \
} while (0)

#define STS128(r0, r1, r2, r3, addr) \
    asm volatile("st.shared.v4.b32 [%0], {%1, %2, %3, %4};" \
        :: "r"(addr), "r"(r0), "r"(r1), "r"(r2), "r"(r3) : "memory")

// ===========================================================================
// Kernel 1: values fp32 -> (a) fp32 copy into out table, (b) fp16 swizzled
// tile table g_vbf, (c) per-tile fp32 column sums (via smem staging, so the
// column reads never touch L1 with 32-line wavefronts).
// Grid: TILES_TOTAL CTAs x 256 threads. Thread covers half a row (32 floats).
// ===========================================================================
__global__ void emn_cvt(const float* __restrict__ values, float* __restrict__ newvals) {
    __shared__ float scol[128][68];   // pad 68: float4-aligned rows, conflict-free cols
    const int t = blockIdx.x;
    const int tid = threadIdx.x;
    const int row = tid >> 1;
    const int half = tid & 1;
    const long gr = (long)t * KV_TILE + row;

    float4 v[8];
    if (gr < (long)M_SZ) {
        const float4* src = (const float4*)(values + gr * D_SZ + half * 32);
#pragma unroll
        for (int i = 0; i < 8; i++) v[i] = src[i];
        float4* dst = (float4*)(newvals + gr * D_SZ + half * 32);
#pragma unroll
        for (int i = 0; i < 8; i++) dst[i] = v[i];
    } else {
#pragma unroll
        for (int i = 0; i < 8; i++) v[i] = make_float4(0.f, 0.f, 0.f, 0.f);
    }

    char* tb = ((char*)g_vbf) + (size_t)t * 16384;
    const uint32_t xm = (uint32_t)((row & 7) << 4);
#pragma unroll
    for (int i = 0; i < 4; i++) {
        uint4 u;
        u.x = pack_h(v[2 * i].x, v[2 * i].y);
        u.y = pack_h(v[2 * i].z, v[2 * i].w);
        u.z = pack_h(v[2 * i + 1].x, v[2 * i + 1].y);
        u.w = pack_h(v[2 * i + 1].z, v[2 * i + 1].w);
        const uint32_t off = (uint32_t)(row * 128 + half * 64 + i * 16);
        *(uint4*)(tb + (off ^ xm)) = u;
    }

    // stage the fp32 tile in smem, then deterministic per-column sums
#pragma unroll
    for (int i = 0; i < 8; i++)
        *(float4*)&scol[row][half * 32 + i * 4] = v[i];
    __syncthreads();
    if (tid < D_SZ) {
        float s = 0.f;
#pragma unroll 8
        for (int r = 0; r < 128; r++) s += scol[r][tid];   // OOB rows are zeros
        g_tilesum[t][tid] = s;
    }
}

// ===========================================================================
// Kernel 1b: reduce per-tile sums -> global column sums (deterministic).
// ===========================================================================
__global__ void emn_colsum() {
    const int w = (blockIdx.x * (blockDim.x >> 5)) + (threadIdx.x >> 5);
    const int lane = threadIdx.x & 31;
    if (w >= D_SZ) return;
    float s = 0.f;
    for (int t = lane; t < TILES_TOTAL; t += 32) s += g_tilesum[t][w];
#pragma unroll
    for (int o = 16; o; o >>= 1) s += __shfl_xor_sync(0xffffffffu, s, o);
    if (lane == 0) g_vcolsum[w] = s;
}

// ===========================================================================
// Kernel 2: erase/add gate precompute (coalesced; weights transposed in smem)
// + read-only flag (block 0). Grid: 16 blocks x 256 threads; block handles
// 64 batch rows. smem: We[64][65] | Wa[64][65] | x[64][64]  (49,664 B dyn).
// ===========================================================================
__global__ void emn_ea(const int* __restrict__ mem_idx,
                       const float* __restrict__ input,
                       const float* __restrict__ Wew, const float* __restrict__ Web,
                       const float* __restrict__ Waw, const float* __restrict__ Wab) {
    extern __shared__ float eas[];
    float* sWe = eas;                 // [64][65] transposed: sWe[k*65+d] = Wew[d*64+k]
    float* sWa = eas + 4160;
    float* sx  = eas + 8320;          // [64][64]
    const int tid = threadIdx.x;
    const int b0 = blockIdx.x * 64;

    if (blockIdx.x == 0) {
        int nz = 0;
        for (int i = tid; i < B_SZ; i += 256) nz |= (mem_idx[i] != 0);
        nz = __syncthreads_or(nz);
        if (tid == 0) g_read_only = !nz;
    }

    for (int i = tid; i < 4096; i += 256) {
        const int d = i >> 6, k = i & 63;
        sWe[k * 65 + d] = Wew[i];
        sWa[k * 65 + d] = Waw[i];
        sx[i] = input[b0 * 64 + i];
    }
    __syncthreads();

    const int d = tid & 63;
    const int rr = tid >> 6;          // 0..3
    const float eb = Web[d], ab = Wab[d];
#pragma unroll 4
    for (int r8 = 0; r8 < 16; r8++) {
        const int r = rr * 16 + r8;
        float e = eb, a = ab;
#pragma unroll
        for (int k = 0; k < 64; k++) {
            const float x = sx[r * 64 + k];      // broadcast within warp
            e = fmaf(x, sWe[k * 65 + d], e);     // conflict-free
            a = fmaf(x, sWa[k * 65 + d], a);
        }
        g_ea[0][b0 + r][d] = 1.0f / (1.0f + __expf(-e));
        g_ea[1][b0 + r][d] = tanhf(a);
    }
}

// ===========================================================================
// Kernel 3: gated scatter apply (last-index-wins on duplicate idx)
// ===========================================================================
__global__ void emn_scatter(const int* __restrict__ mem_idx,
                            const float* __restrict__ values,
                            float* __restrict__ newvals) {
    if (g_read_only) return;
    const int b = blockIdx.x;
    const int idx = mem_idx[b];
    __shared__ int dup;
    if (threadIdx.x == 0) dup = 0;
    __syncthreads();
    for (int bp = b + 1 + threadIdx.x; bp < B_SZ; bp += 64)
        if (mem_idx[bp] == idx) dup = 1;
    __syncthreads();
    if (dup) return;
    const int d = threadIdx.x;
    const long off = (long)idx * D_SZ + d;
    newvals[off] = (1.0f - g_ea[0][b][d]) * values[off] + g_ea[1][b][d];
}

// ===========================================================================
// Kernel 4: flash attention partials via warp-level HMMA (mma.sync fp16).
// Precision scheme:
//   * fp16 Q/K (10-bit mantissa): the correlated q-rounding error (the old
//     1.28e-3 bf16 failure) shrinks 8x to ~1.6e-4 -> single-Q GEMM1 suffices.
//   * P_dev = exp(S)-1 (|P_dev|~0.03) through GEMM2; the O(1) part of exp is
//     the exact fp32 V column sum, added in the combine kernel.
// Grid (QTILES=8, SPLITS=74), 256 threads (8 warps), 2 CTAs/SM.
// ===========================================================================
__global__ void __launch_bounds__(256, 2)
emn_attn(const float* __restrict__ input) {
    extern __shared__ char dsm[];   // Q 18432 | K0 16384 | K1 16384
    __shared__ __align__(8) unsigned long long s_mbar[2];

    const uint32_t smQ = smem_u32(dsm);
    const uint32_t smK[2] = { smQ + 18432u, smQ + 34816u };
    const uint32_t mb[2] = { smem_u32(&s_mbar[0]), smem_u32(&s_mbar[1]) };

    const int tid  = threadIdx.x;
    const int wid  = tid >> 5;
    const int lane = tid & 31;
    const int gi   = lane >> 2;       // groupID
    const int tig  = lane & 3;        // thread-in-group
    const int wbase = wid * 16;       // q rows of this warp within the tile
    const int qb = blockIdx.x * 128;
    const int s  = blockIdx.y;
    const int t0 = s * TPS;
    int ntiles = TILES_TOTAL - t0;
    if (ntiles < 0) ntiles = 0;
    if (ntiles > TPS) ntiles = TPS;

    // --- Q tile -> fp16 smem, 144B row stride (conflict-free for ldmatrix) ---
    {
        const int row = tid >> 1;
        const int half = tid & 1;
        const float4* qp = (const float4*)(input + (qb + row) * D_SZ + half * 32);
        float4 q[8];
#pragma unroll
        for (int i = 0; i < 8; i++) q[i] = qp[i];
        const uint32_t base = smQ + (uint32_t)(row * 144 + half * 64);
#pragma unroll
        for (int i = 0; i < 4; i++) {
            uint32_t u0 = pack_h(q[2 * i].x, q[2 * i].y);
            uint32_t u1 = pack_h(q[2 * i].z, q[2 * i].w);
            uint32_t u2 = pack_h(q[2 * i + 1].x, q[2 * i + 1].y);
            uint32_t u3 = pack_h(q[2 * i + 1].z, q[2 * i + 1].w);
            STS128(u0, u1, u2, u3, base + i * 16);
        }
    }
    if (tid < 2) MBARRIER_INIT(mb[tid], 1);
    __syncthreads();

    // --- Q fragments (ldmatrix x4 per 16-wide k block) ---
    uint32_t qa[4][4];
    {
        const int rQ = wbase + (lane & 7) + (((lane >> 3) & 1) << 3);
        const uint32_t qaddr = smQ + (uint32_t)(rQ * 144 + (lane >> 4) * 16);
#pragma unroll
        for (int kb = 0; kb < 4; kb++) ldsm4(qa[kb], qaddr + kb * 32);
    }

    // --- prologue: tile 0 into buffer 0 ---
    int ph[2] = { 0, 0 };
    if (ntiles > 0 && tid == 0) {
        MBARRIER_EXPECT_TX(mb[0], 16384);
        BULK_G2S(smK[0], (const char*)g_vbf + (size_t)t0 * 16384, 16384, mb[0]);
    }

    const uint32_t xorm = (uint32_t)((lane & 7) << 4);
    const uint32_t klo_a = (uint32_t)((lane & 7) * 128) + ((((lane >> 3) & 3) << 4) ^ xorm);
    const uint32_t klo_b = (uint32_t)((lane & 7) * 128) + ((64u + (((lane >> 3) & 3) << 4)) ^ xorm);
    const uint32_t vlo   = (uint32_t)((lane & 15) * 128);

    float oacc[8][4];
#pragma unroll
    for (int n = 0; n < 8; n++)
#pragma unroll
        for (int i = 0; i < 4; i++) oacc[n][i] = 0.f;
    float ls0 = 0.f, ls1 = 0.f;
    int buf = 0;

    for (int it = 0; it < ntiles; ++it) {
        const uint32_t kbase = smK[buf];
        MBARRIER_WAIT_PARITY(mb[buf], ph[buf]);
        ph[buf] ^= 1;

        if (tid == 0 && it + 1 < ntiles) {
            MBARRIER_EXPECT_TX(mb[buf ^ 1], 16384);
            BULK_G2S(smK[buf ^ 1], (const char*)g_vbf + (size_t)(t0 + it + 1) * 16384,
                     16384, mb[buf ^ 1]);
        }

        const int kv = (t0 + it) * KV_TILE;
        const int lim = M_SZ - kv;            // >= 128 except global last tile
        const bool full = (lim >= KV_TILE);

        // --- GEMM1: S = Q @ K^T ; epilogue: P_dev = exp(S)-1 fragments ---
        uint32_t pf[8][4];
#pragma unroll
        for (int j = 0; j < 16; j++) {
            uint32_t ba[4], bb[4];
            ldsm4(ba, kbase + (uint32_t)(j * 1024) + klo_a);
            ldsm4(bb, kbase + (uint32_t)(j * 1024) + klo_b);
            float c[4] = { 0.f, 0.f, 0.f, 0.f };
            mma_f16(c, qa[0], ba[0], ba[1]);
            mma_f16(c, qa[1], ba[2], ba[3]);
            mma_f16(c, qa[2], bb[0], bb[1]);
            mma_f16(c, qa[3], bb[2], bb[3]);

            float e0, e1, e2, e3;
            if (full) {
                e0 = __expf(c[0]) - 1.0f; e1 = __expf(c[1]) - 1.0f;
                e2 = __expf(c[2]) - 1.0f; e3 = __expf(c[3]) - 1.0f;
            } else {
                const int col = (j << 3) + (tig << 1);
                e0 = (col     < lim) ? __expf(c[0]) - 1.0f : 0.f;
                e1 = (col + 1 < lim) ? __expf(c[1]) - 1.0f : 0.f;
                e2 = (col     < lim) ? __expf(c[2]) - 1.0f : 0.f;
                e3 = (col + 1 < lim) ? __expf(c[3]) - 1.0f : 0.f;
            }
            ls0 += e0 + e1;
            ls1 += e2 + e3;
            const uint32_t p01 = pack_h(e0, e1);
            const uint32_t p23 = pack_h(e2, e3);
            if (!(j & 1)) { pf[j >> 1][0] = p01; pf[j >> 1][1] = p23; }
            else          { pf[j >> 1][2] = p01; pf[j >> 1][3] = p23; }
        }

        // --- GEMM2: O += P_dev @ V (same smem tile via ldmatrix.trans) ---
#pragma unroll
        for (int kb = 0; kb < 8; kb++) {
#pragma unroll
            for (int n = 0; n < 8; n += 2) {
                uint32_t bv[4];
                ldsm4t(bv, kbase + vlo + (uint32_t)(kb * 2048)
                             + ((((uint32_t)(n + (lane >> 4))) << 4) ^ xorm));
                mma_f16(oacc[n],     pf[kb], bv[0], bv[1]);
                mma_f16(oacc[n + 1], pf[kb], bv[2], bv[3]);
            }
        }

        __syncthreads();   // everyone done reading this buffer before refill
        buf ^= 1;
    }

    // --- write O partials ---
    const int r0 = qb + wbase + gi;
#pragma unroll
    for (int n = 0; n < 8; n++) {
        const int col = n * 8 + tig * 2;
        *(float2*)&g_Opart[s][r0][col]     = make_float2(oacc[n][0], oacc[n][1]);
        *(float2*)&g_Opart[s][r0 + 8][col] = make_float2(oacc[n][2], oacc[n][3]);
    }
    // --- row-sum partials ---
    ls0 += __shfl_xor_sync(0xffffffffu, ls0, 1);
    ls0 += __shfl_xor_sync(0xffffffffu, ls0, 2);
    ls1 += __shfl_xor_sync(0xffffffffu, ls1, 1);
    ls1 += __shfl_xor_sync(0xffffffffu, ls1, 2);
    if (tig == 0) {
        g_lpart[s][r0]     = ls0;
        g_lpart[s][r0 + 8] = ls1;
    }
}

// ===========================================================================
// Kernel 5: combine splits.
// retrieved[b][d] = (colsum[d] + sum_s O_s) / (M + sum_s l_s)
// ===========================================================================
__global__ void emn_attn_reduce(float* __restrict__ retrieved) {
    const int b = blockIdx.x;
    const int d = threadIdx.x;
    float o = g_vcolsum[d];
    float l = (float)M_SZ;
#pragma unroll 2
    for (int s = 0; s < SPLITS; s++) {
        o += g_Opart[s][b][d];
        l += g_lpart[s][b];
    }
    retrieved[b * D_SZ + d] = o / l;
}

// ===========================================================================
extern "C" void kernel_launch(void* const* d_in, const int* in_sizes, int n_in,
                              void* d_out, int out_size) {
    const int*   mem_idx = (const int*)d_in[0];
    const float* input   = (const float*)d_in[1];
    const float* values  = (const float*)d_in[2];
    const float* Wew     = (const float*)d_in[3];
    const float* Web     = (const float*)d_in[4];
    const float* Waw     = (const float*)d_in[5];
    const float* Wab     = (const float*)d_in[6];

    float* out       = (float*)d_out;
    float* retrieved = out;                    // [B, D]
    float* newvals   = out + B_SZ * D_SZ;      // [M, D]

    // 1) fused: copy values -> out table + fp16 swizzled tiles + tile colsums
    emn_cvt<<<TILES_TOTAL, 256>>>(values, newvals);
    // 1b) global column sums (deterministic tree)
    emn_colsum<<<8, 256>>>();
    // 2) erase/add gates (coalesced) + read-only flag
    const int ea_smem = (4160 * 2 + 4096) * (int)sizeof(float);   // 49,664 B
    cudaFuncSetAttribute(emn_ea, cudaFuncAttributeMaxDynamicSharedMemorySize, ea_smem);
    emn_ea<<<16, 256, ea_smem>>>(mem_idx, input, Wew, Web, Waw, Wab);
    // 3) gated scatter apply
    emn_scatter<<<B_SZ, 64>>>(mem_idx, values, newvals);
    // 4) attention partials (fp16 tensor cores, single-Q)
    const int dyn_smem = 18432 + 2 * 16384;    // 51200 B
    cudaFuncSetAttribute(emn_attn, cudaFuncAttributeMaxDynamicSharedMemorySize, dyn_smem);
    emn_attn<<<dim3(QTILES, SPLITS), 256, dyn_smem>>>(input);
    // 5) combine
    emn_attn_reduce<<<B_SZ, D_SZ>>>(retrieved);
}